// round 7
// baseline (speedup 1.0000x reference)
#include <cuda_runtime.h>
#include <cstdint>

// Problem shape (fixed): B=32, N=4096, E=8192, D=128
#define BB   32
#define NN   4096
#define EE   8192
#define DD   128
#define MM   (BB * NN)          // 131072 rows
#define NEDGE (BB * EE)         // 262144 edges

// device scratch: 64MB aggregation + 384KB fragment-major tf32 weights + 201MB Xh
__device__ __align__(16) float    g_agg[(size_t)MM * DD];
__device__ __align__(16) uint32_t g_Btf[6 * 16384];
__device__ __align__(16) float4   g_Xh[(size_t)2048 * 3 * 8 * 256];   // [blk][q][i][tid]

// ---------------------------------------------------------------------------
// helpers
// ---------------------------------------------------------------------------
__device__ __forceinline__ uint32_t f2tf32(float x) {
    uint32_t r;
    asm("cvt.rna.tf32.f32 %0, %1;" : "=r"(r) : "f"(x));
    return r;
}
__device__ __forceinline__ float sigmoidf_fast(float x) {
    return 1.0f / (1.0f + __expf(-x));
}
__device__ __forceinline__ float tanh_safe(float x) {
    float e = __expf(-2.0f * fabsf(x));
    float t = (1.0f - e) / (1.0f + e);
    return copysignf(t, x);
}
__device__ __forceinline__ void mma_tf32(float* c, const uint32_t a[4], const uint32_t b[2]) {
    asm volatile(
        "mma.sync.aligned.m16n8k8.row.col.f32.tf32.tf32.f32 "
        "{%0,%1,%2,%3}, {%4,%5,%6,%7}, {%8,%9}, {%0,%1,%2,%3};\n"
        : "+f"(c[0]), "+f"(c[1]), "+f"(c[2]), "+f"(c[3])
        : "r"(a[0]), "r"(a[1]), "r"(a[2]), "r"(a[3]),
          "r"(b[0]), "r"(b[1]));
}
__device__ __forceinline__ void cp_async16(uint32_t saddr, const void* g) {
    asm volatile("cp.async.cg.shared.global [%0], [%1], 16;\n" :: "r"(saddr), "l"(g));
}

// ---------------------------------------------------------------------------
// scatter-add messages into g_agg (one warp per edge, red.v4) — unchanged
// ---------------------------------------------------------------------------
__global__ void scatter_kernel(const float* __restrict__ msgs,
                               const int*   __restrict__ conn) {
    const int gwarp = (blockIdx.x * blockDim.x + threadIdx.x) >> 5;
    const int lane  = threadIdx.x & 31;
    if (gwarp >= NEDGE) return;
    const int tgt = __ldg(&conn[2 * gwarp + 1]);
    const int b   = gwarp >> 13;
    const float4 m = reinterpret_cast<const float4*>(msgs)[(size_t)gwarp * 32 + lane];
    float* dst = &g_agg[((size_t)b * NN + tgt) * DD + lane * 4];
    asm volatile("red.global.add.v4.f32 [%0], {%1, %2, %3, %4};"
                 :: "l"(dst), "f"(m.x), "f"(m.y), "f"(m.z), "f"(m.w) : "memory");
}

// ---------------------------------------------------------------------------
// fragment-major tf32 weight images; exec order e: 0=W0 1=W1 2=W2 3=U1 4=U0 5=U2
// ---------------------------------------------------------------------------
__global__ void convert_B_kernel(const float* __restrict__ W,
                                 const float* __restrict__ U) {
    const int t = blockIdx.x * blockDim.x + threadIdx.x;
    if (t >= 6 * 4096) return;
    const int e   = t >> 12;
    const int iu  = t & 4095;
    const int tig = iu & 3;
    const int g   = (iu >> 2) & 7;
    const int p   = (iu >> 5) & 1;
    const int wN  = (iu >> 6) & 3;
    const int ks  = iu >> 8;
    int m, q;
    if (e < 3) { m = 0; q = e; }
    else       { m = 1; q = (e == 3) ? 1 : ((e == 4) ? 0 : 2); }
    const float* src = m ? U : W;
    const int k1 = ks * 8 + tig, k2 = k1 + 4;
    const int C  = wN * 32 + p * 16 + g;
    uint4 v;
    v.x = f2tf32(src[k1 * 384 + q * 128 + C]);
    v.y = f2tf32(src[k2 * 384 + q * 128 + C]);
    v.z = f2tf32(src[k1 * 384 + q * 128 + C + 8]);
    v.w = f2tf32(src[k2 * 384 + q * 128 + C + 8]);
    reinterpret_cast<uint4*>(g_Btf)[t] = v;
}

// ---------------------------------------------------------------------------
// shared GEMM machinery (verified in R6)
// ---------------------------------------------------------------------------
#define SM_AF   0
#define SM_B0   32768
#define SM_B1   65536
#define SM_A2   98304
#define SM_BIAS (98304 + 33792)
#define SMEM_F  (SM_BIAS + 3072)
#define SMEM_G  98304
#define PITCH 132

__device__ __forceinline__ void load_stage(uint32_t buf, int s, int tid) {
    const uint32_t off = (uint32_t)((s >> 1) * 16384 + (s & 1) * 8192);
#pragma unroll
    for (int i = 0; i < 8; i++) {
        const int e = tid + i * 256;
        cp_async16(buf + (uint32_t)e * 16, &g_Btf[off + e * 4]);
    }
}

template <bool RAW>
__device__ __forceinline__ void build_A(unsigned char* smem, const float* __restrict__ src,
                                        int row0, int tid) {
    uint32_t* sAf = reinterpret_cast<uint32_t*>(smem + SM_AF);
    float*    sA2 = reinterpret_cast<float*>(smem + SM_A2);
#pragma unroll
    for (int it = 0; it < 8; it++) {
        const int idx = tid + it * 256;
        const int row = idx >> 5;
        const int c4  = (idx & 31) << 2;
        float4 v = *reinterpret_cast<const float4*>(&src[(size_t)(row0 + row) * DD + c4]);
        if (RAW) *reinterpret_cast<float4*>(&sA2[row * PITCH + c4]) = v;
        const int wm = row >> 5, rl = row & 31;
        const int cr = (rl >> 3) & 1, ii = (rl >> 4) & 1, g = rl & 7;
        const int ks = c4 >> 3, ch = (c4 >> 2) & 1;
        const int comp = ch * 2 + cr;
        const int base = (((ks * 2 + wm) * 2 + ii) * 32 + g * 4) * 4 + comp;
        sAf[base + 0 * 4] = f2tf32(v.x);
        sAf[base + 1 * 4] = f2tf32(v.y);
        sAf[base + 2 * 4] = f2tf32(v.z);
        sAf[base + 3 * 4] = f2tf32(v.w);
    }
}

__device__ __forceinline__ void compute_half(float* __restrict__ acc,
                                             const uint4* __restrict__ sAf4,
                                             const uint4* __restrict__ sB4,
                                             int kb8, int wm, int wN, int lane) {
#pragma unroll
    for (int ks = 0; ks < 8; ks++) {
        const int ksg = kb8 + ks;
        const uint4 av0 = sAf4[((ksg * 2 + wm) * 2 + 0) * 32 + lane];
        const uint4 av1 = sAf4[((ksg * 2 + wm) * 2 + 1) * 32 + lane];
        const uint4 bv0 = sB4[((ks * 4 + wN) * 2 + 0) * 32 + lane];
        const uint4 bv1 = sB4[((ks * 4 + wN) * 2 + 1) * 32 + lane];
        const uint32_t a0[4] = {av0.x, av0.y, av0.z, av0.w};
        const uint32_t a1[4] = {av1.x, av1.y, av1.z, av1.w};
        uint32_t b[2];
        b[0] = bv0.x; b[1] = bv0.y; mma_tf32(acc + 0,  a0, b); mma_tf32(acc + 16, a1, b);
        b[0] = bv0.z; b[1] = bv0.w; mma_tf32(acc + 4,  a0, b); mma_tf32(acc + 20, a1, b);
        b[0] = bv1.x; b[1] = bv1.y; mma_tf32(acc + 8,  a0, b); mma_tf32(acc + 24, a1, b);
        b[0] = bv1.z; b[1] = bv1.w; mma_tf32(acc + 12, a0, b); mma_tf32(acc + 28, a1, b);
    }
}

// STAGE: prefetch stage s+1 (within [FIRST,LAST]), wait, compute s.
#define STAGE(s, ACC, LAST)                                                         \
    {                                                                               \
        if ((s) + 1 <= (LAST)) {                                                    \
            load_stage(sb_addr[((s) + 1) & 1], (s) + 1, tid);                       \
            asm volatile("cp.async.commit_group;");                                 \
            asm volatile("cp.async.wait_group 1;" ::: "memory");                    \
        } else {                                                                    \
            asm volatile("cp.async.wait_group 0;" ::: "memory");                    \
        }                                                                           \
        __syncthreads();                                                            \
        compute_half(ACC, sAf4, ((s) & 1) ? sB1_4 : sB0_4, ((s) & 1) * 8,           \
                     warpM, warpN, lane);                                           \
        __syncthreads();                                                            \
    }

// ---------------------------------------------------------------------------
// gemm2: Xh = h @ U  (chunks e=3(U1->q1), 4(U0->q0), 5(U2->q2)) -> g_Xh
// ---------------------------------------------------------------------------
__global__ __launch_bounds__(256, 1)
void gemm2_kernel(const float* __restrict__ atom_state) {
    extern __shared__ unsigned char smem[];
    const uint4* sAf4  = reinterpret_cast<const uint4*>(smem + SM_AF);
    const uint4* sB0_4 = reinterpret_cast<const uint4*>(smem + SM_B0);
    const uint4* sB1_4 = reinterpret_cast<const uint4*>(smem + SM_B1);
    uint32_t sb_addr[2];
    sb_addr[0] = (uint32_t)__cvta_generic_to_shared(smem + SM_B0);
    sb_addr[1] = (uint32_t)__cvta_generic_to_shared(smem + SM_B1);

    const int tid   = threadIdx.x;
    const int lane  = tid & 31;
    const int warp  = tid >> 5;
    const int warpM = warp >> 2;
    const int warpN = warp & 3;
    const int row0  = blockIdx.x * 64;

    load_stage(sb_addr[0], 6, tid);          // chunk3 half0 (stage6 -> buf0)
    asm volatile("cp.async.commit_group;");
    build_A<false>(smem, atom_state, row0, tid);

    float acc[32];
    const int qmap[3] = {1, 0, 2};
#pragma unroll
    for (int e = 0; e < 3; e++) {
#pragma unroll
        for (int u = 0; u < 32; u++) acc[u] = 0.f;
        STAGE(6 + 2 * e,     acc, 11)
        STAGE(6 + 2 * e + 1, acc, 11)
        const size_t base = ((size_t)blockIdx.x * 3 + qmap[e]) * 8 * 256;
#pragma unroll
        for (int i = 0; i < 8; i++)
            g_Xh[base + (size_t)i * 256 + tid] =
                make_float4(acc[4 * i], acc[4 * i + 1], acc[4 * i + 2], acc[4 * i + 3]);
    }
}

// ---------------------------------------------------------------------------
// final: GEMM1 (W chunks) + gates, consuming g_Xh (prefetched per chunk)
// ---------------------------------------------------------------------------
__global__ __launch_bounds__(256, 1)
void final_kernel(const float* __restrict__ atom_state,
                  const float* __restrict__ bias,
                  float* __restrict__ out) {
    extern __shared__ unsigned char smem[];
    const uint4* sAf4  = reinterpret_cast<const uint4*>(smem + SM_AF);
    const uint4* sB0_4 = reinterpret_cast<const uint4*>(smem + SM_B0);
    const uint4* sB1_4 = reinterpret_cast<const uint4*>(smem + SM_B1);
    float* sA2   = reinterpret_cast<float*>(smem + SM_A2);
    float* sBias = reinterpret_cast<float*>(smem + SM_BIAS);
    float* sStage = reinterpret_cast<float*>(smem + SM_B0);   // dead after stage 5
    uint32_t sb_addr[2];
    sb_addr[0] = (uint32_t)__cvta_generic_to_shared(smem + SM_B0);
    sb_addr[1] = (uint32_t)__cvta_generic_to_shared(smem + SM_B1);

    const int tid   = threadIdx.x;
    const int lane  = tid & 31;
    const int warp  = tid >> 5;
    const int warpM = warp >> 2;
    const int warpN = warp & 3;
    const int gID   = lane >> 2;
    const int tig   = lane & 3;
    const int row0  = blockIdx.x * 64;
    const size_t xbase = (size_t)blockIdx.x * 3 * 8 * 256;

    load_stage(sb_addr[0], 0, tid);
    asm volatile("cp.async.commit_group;");
    build_A<true>(smem, g_agg, row0, tid);     // A = agg (frag), also reuse sA2 slot
    if (tid < 192) {
        float4 v = *reinterpret_cast<const float4*>(&bias[tid * 4]);
        *reinterpret_cast<float4*>(&sBias[tid * 4]) = v;
    }

    float Z[32], R[32], acc[32];
    float4 xh4[8];

    // ---- chunk 0 -> z ----
#pragma unroll
    for (int i = 0; i < 8; i++)
        xh4[i] = __ldg(&g_Xh[xbase + (size_t)(0 * 8 + i) * 256 + tid]);
#pragma unroll
    for (int u = 0; u < 32; u++) acc[u] = 0.f;
    STAGE(0, acc, 5)
    STAGE(1, acc, 5)
#pragma unroll
    for (int u = 0; u < 32; u++) {
        const int j = (u >> 2) & 3, c = u & 3;
        const int col = warpN * 32 + j * 8 + tig * 2 + (c & 1);
        const float hcv = (&xh4[u >> 2].x)[u & 3];
        Z[u] = sigmoidf_fast(acc[u] + sBias[col] + hcv + sBias[384 + col]);
    }

    // ---- chunk 1 -> r ----
#pragma unroll
    for (int i = 0; i < 8; i++)
        xh4[i] = __ldg(&g_Xh[xbase + (size_t)(1 * 8 + i) * 256 + tid]);
#pragma unroll
    for (int u = 0; u < 32; u++) acc[u] = 0.f;
    STAGE(2, acc, 5)
    STAGE(3, acc, 5)
#pragma unroll
    for (int u = 0; u < 32; u++) {
        const int j = (u >> 2) & 3, c = u & 3;
        const int col = warpN * 32 + j * 8 + tig * 2 + (c & 1);
        const float hcv = (&xh4[u >> 2].x)[u & 3];
        R[u] = sigmoidf_fast(acc[u] + sBias[128 + col] + hcv + sBias[384 + 128 + col]);
    }

    // ---- chunk 2 -> hh, combine ----
#pragma unroll
    for (int i = 0; i < 8; i++)
        xh4[i] = __ldg(&g_Xh[xbase + (size_t)(2 * 8 + i) * 256 + tid]);
#pragma unroll
    for (int u = 0; u < 32; u++) acc[u] = 0.f;
    STAGE(4, acc, 5)
    STAGE(5, acc, 5)
    // refresh raw h into sA2 (was overwritten? no — sA2 holds agg raw from build_A<true>)
    // NOTE: build_A<true> stored g_agg raw; we need raw atom_state h for the combine.
    // load h raw now into sA2 (B buffers are dead, but sA2 is its own region).
    __syncthreads();
#pragma unroll
    for (int it = 0; it < 8; it++) {
        const int idx = tid + it * 256;
        const int row = idx >> 5;
        const int c4  = (idx & 31) << 2;
        float4 v = *reinterpret_cast<const float4*>(
            &atom_state[(size_t)(row0 + row) * DD + c4]);
        *reinterpret_cast<float4*>(&sA2[row * PITCH + c4]) = v;
    }
    __syncthreads();
#pragma unroll
    for (int u = 0; u < 32; u++) {
        const int i = u >> 4, j = (u >> 2) & 3, c = u & 3;
        const int rt  = warpM * 32 + i * 16 + gID + ((c >> 1) << 3);
        const int col = warpN * 32 + j * 8 + tig * 2 + (c & 1);
        const float hcv = (&xh4[u >> 2].x)[u & 3];
        const float rh = hcv + sBias[384 + 256 + col];
        const float hh = tanh_safe(acc[u] + sBias[256 + col] + R[u] * rh);
        const float h  = sA2[rt * PITCH + col];
        sStage[rt * PITCH + col] = Z[u] * h + (1.0f - Z[u]) * hh;
    }
    __syncthreads();

#pragma unroll
    for (int it = 0; it < 8; it++) {
        const int idx = tid + it * 256;
        const int row = idx >> 5;
        const int c4  = (idx & 31) << 2;
        float4 v = *reinterpret_cast<const float4*>(&sStage[row * PITCH + c4]);
        *reinterpret_cast<float4*>(&out[(size_t)(row0 + row) * DD + c4]) = v;
    }
}

// ---------------------------------------------------------------------------
// launch: fork [convert -> gemm2] onto side stream, overlap [memset -> scatter]
// ---------------------------------------------------------------------------
extern "C" void kernel_launch(void* const* d_in, const int* in_sizes, int n_in,
                              void* d_out, int out_size) {
    const float* atom_state = (const float*)d_in[0];
    const float* messages   = (const float*)d_in[1];
    const int*   conn       = (const int*)d_in[2];
    const float* Wk         = (const float*)d_in[3];
    const float* Uk         = (const float*)d_in[4];
    const float* bias       = (const float*)d_in[5];
    float*       out        = (float*)d_out;
    (void)in_sizes; (void)n_in; (void)out_size;

    static cudaStream_t s1 = nullptr;
    static cudaEvent_t evA = nullptr, evB = nullptr;
    if (s1 == nullptr) {
        cudaStreamCreateWithFlags(&s1, cudaStreamNonBlocking);
        cudaEventCreateWithFlags(&evA, cudaEventDisableTiming);
        cudaEventCreateWithFlags(&evB, cudaEventDisableTiming);
        cudaFuncSetAttribute(gemm2_kernel,
                             cudaFuncAttributeMaxDynamicSharedMemorySize, SMEM_G);
        cudaFuncSetAttribute(final_kernel,
                             cudaFuncAttributeMaxDynamicSharedMemorySize, SMEM_F);
    }

    void* agg_ptr = nullptr;
    cudaGetSymbolAddress(&agg_ptr, g_agg);

    // fork side branch: convert -> gemm2
    cudaEventRecord(evA, 0);
    cudaStreamWaitEvent(s1, evA, 0);
    convert_B_kernel<<<96, 256, 0, s1>>>(Wk, Uk);
    gemm2_kernel<<<MM / 64, 256, SMEM_G, s1>>>(atom_state);
    cudaEventRecord(evB, s1);

    // main branch: memset -> scatter
    cudaMemsetAsync(agg_ptr, 0, (size_t)MM * DD * sizeof(float));
    scatter_kernel<<<NEDGE / 8, 256>>>(messages, conn);

    // join, then final
    cudaStreamWaitEvent(0, evB, 0);
    final_kernel<<<MM / 64, 256, SMEM_F>>>(atom_state, bias, out);
}

// round 9
// speedup vs baseline: 1.2753x; 1.2753x over previous
#include <cuda_runtime.h>
#include <cstdint>

// Problem shape (fixed): B=32, N=4096, E=8192, D=128
#define BB   32
#define NN   4096
#define EE   8192
#define DD   128
#define MM   (BB * NN)          // 131072 rows
#define NEDGE (BB * EE)         // 262144 edges

// device scratch: 64MB aggregation + 384KB fragment-major tf32 weight images
__device__ __align__(16) float    g_agg[(size_t)MM * DD];
__device__ __align__(16) uint32_t g_Btf[6 * 16384];   // [e][ks][wN][p][lane] uint4s

// ---------------------------------------------------------------------------
// helpers
// ---------------------------------------------------------------------------
__device__ __forceinline__ uint32_t f2tf32(float x) {
    uint32_t r;
    asm("cvt.rna.tf32.f32 %0, %1;" : "=r"(r) : "f"(x));
    return r;
}
__device__ __forceinline__ float sigmoidf_fast(float x) {
    return 1.0f / (1.0f + __expf(-x));
}
__device__ __forceinline__ float tanh_safe(float x) {
    float e = __expf(-2.0f * fabsf(x));
    float t = (1.0f - e) / (1.0f + e);
    return copysignf(t, x);
}
__device__ __forceinline__ void mma_tf32(float* c, const uint32_t a[4], const uint32_t b[2]) {
    asm volatile(
        "mma.sync.aligned.m16n8k8.row.col.f32.tf32.tf32.f32 "
        "{%0,%1,%2,%3}, {%4,%5,%6,%7}, {%8,%9}, {%0,%1,%2,%3};\n"
        : "+f"(c[0]), "+f"(c[1]), "+f"(c[2]), "+f"(c[3])
        : "r"(a[0]), "r"(a[1]), "r"(a[2]), "r"(a[3]),
          "r"(b[0]), "r"(b[1]));
}
__device__ __forceinline__ void cp_async16(uint32_t saddr, const void* g) {
    asm volatile("cp.async.cg.shared.global [%0], [%1], 16;\n" :: "r"(saddr), "l"(g));
}

// ---------------------------------------------------------------------------
// scatter-add messages into g_agg (one warp per edge, red.v4) — unchanged
// ---------------------------------------------------------------------------
__global__ void scatter_kernel(const float* __restrict__ msgs,
                               const int*   __restrict__ conn) {
    const int gwarp = (blockIdx.x * blockDim.x + threadIdx.x) >> 5;
    const int lane  = threadIdx.x & 31;
    if (gwarp >= NEDGE) return;
    const int tgt = __ldg(&conn[2 * gwarp + 1]);
    const int b   = gwarp >> 13;
    const float4 m = reinterpret_cast<const float4*>(msgs)[(size_t)gwarp * 32 + lane];
    float* dst = &g_agg[((size_t)b * NN + tgt) * DD + lane * 4];
    asm volatile("red.global.add.v4.f32 [%0], {%1, %2, %3, %4};"
                 :: "l"(dst), "f"(m.x), "f"(m.y), "f"(m.z), "f"(m.w) : "memory");
}

// ---------------------------------------------------------------------------
// fragment-major tf32 weight images.
// Chunk exec order e: 0=U0 1=W0 2=U1 3=W1 4=U2 5=W2  (m = e&1 ? W : U; q = e>>1)
// uint4 flat index = e*4096 + ks*256 + (wN*2+p)*32 + gID*4 + tig, ks 0..15
// components = { B[8ks+tig][C], B[8ks+tig+4][C], B[8ks+tig][C+8], B[8ks+tig+4][C+8] }
//   C = wN*32 + p*16 + gID ; B[k][c] = src[k*384 + q*128 + c]
// ---------------------------------------------------------------------------
__global__ void convert_B_kernel(const float* __restrict__ W,
                                 const float* __restrict__ U) {
    const int t = blockIdx.x * blockDim.x + threadIdx.x;
    if (t >= 6 * 4096) return;
    const int e   = t >> 12;
    const int iu  = t & 4095;
    const int tig = iu & 3;
    const int g   = (iu >> 2) & 7;
    const int p   = (iu >> 5) & 1;
    const int wN  = (iu >> 6) & 3;
    const int ks  = iu >> 8;
    const int q   = e >> 1;
    const float* src = (e & 1) ? W : U;
    const int k1 = ks * 8 + tig, k2 = k1 + 4;
    const int C  = wN * 32 + p * 16 + g;
    uint4 v;
    v.x = f2tf32(src[k1 * 384 + q * 128 + C]);
    v.y = f2tf32(src[k2 * 384 + q * 128 + C]);
    v.z = f2tf32(src[k1 * 384 + q * 128 + C + 8]);
    v.w = f2tf32(src[k2 * 384 + q * 128 + C + 8]);
    reinterpret_cast<uint4*>(g_Btf)[t] = v;
}

// ---------------------------------------------------------------------------
// fused dual-GEMM + GRU gates, occupancy-2 design
// smem: AH frag 32K | AG frag 32K | SB0 16K | SB1 16K | bias 2K  = 98.5K
// 24 quarter-stages (16KB each), double-buffered.
// ---------------------------------------------------------------------------
#define SM_AH   0
#define SM_AG   32768
#define SM_SB0  65536
#define SM_SB1  81920
#define SM_BIAS 98304
#define SMEM_TOTAL (SM_BIAS + 2048)

__device__ __forceinline__ void load_q(uint32_t buf, int s, int tid) {
#pragma unroll
    for (int i = 0; i < 4; i++) {
        const int e = tid + i * 256;                  // 0..1023 uint4s (16KB)
        cp_async16(buf + (uint32_t)e * 16, &g_Btf[(size_t)s * 4096 + e * 4]);
    }
}

// build fragment-major tf32 A tile (64 rows x 128 k) at frag base
__device__ __forceinline__ void build_A(uint32_t* __restrict__ sAf,
                                        const float* __restrict__ src,
                                        int row0, int tid) {
#pragma unroll
    for (int it = 0; it < 8; it++) {
        const int idx = tid + it * 256;
        const int row = idx >> 5;
        const int c4  = (idx & 31) << 2;
        float4 v = *reinterpret_cast<const float4*>(&src[(size_t)(row0 + row) * DD + c4]);
        const int wm = row >> 5, rl = row & 31;
        const int cr = (rl >> 3) & 1, ii = (rl >> 4) & 1, g = rl & 7;
        const int ks = c4 >> 3, ch = (c4 >> 2) & 1;
        const int comp = ch * 2 + cr;
        const int base = (((ks * 2 + wm) * 2 + ii) * 32 + g * 4) * 4 + comp;
        sAf[base + 0 * 4] = f2tf32(v.x);
        sAf[base + 1 * 4] = f2tf32(v.y);
        sAf[base + 2 * 4] = f2tf32(v.z);
        sAf[base + 3 * 4] = f2tf32(v.w);
    }
}

// compute one quarter (4 ks) on given A fragment and B quarter buffer
__device__ __forceinline__ void compute_q(float* __restrict__ acc,
                                          const uint4* __restrict__ sA4,
                                          const uint4* __restrict__ sB4,
                                          int qb, int wm, int wN, int lane) {
#pragma unroll
    for (int ks = 0; ks < 4; ks++) {
        const int ksg = qb + ks;
        const uint4 av0 = sA4[((ksg * 2 + wm) * 2 + 0) * 32 + lane];
        const uint4 av1 = sA4[((ksg * 2 + wm) * 2 + 1) * 32 + lane];
        const uint4 bv0 = sB4[((ks * 4 + wN) * 2 + 0) * 32 + lane];
        const uint4 bv1 = sB4[((ks * 4 + wN) * 2 + 1) * 32 + lane];
        const uint32_t a0[4] = {av0.x, av0.y, av0.z, av0.w};
        const uint32_t a1[4] = {av1.x, av1.y, av1.z, av1.w};
        uint32_t b[2];
        b[0] = bv0.x; b[1] = bv0.y; mma_tf32(acc + 0,  a0, b); mma_tf32(acc + 16, a1, b);
        b[0] = bv0.z; b[1] = bv0.w; mma_tf32(acc + 4,  a0, b); mma_tf32(acc + 20, a1, b);
        b[0] = bv1.x; b[1] = bv1.y; mma_tf32(acc + 8,  a0, b); mma_tf32(acc + 24, a1, b);
        b[0] = bv1.z; b[1] = bv1.w; mma_tf32(acc + 12, a0, b); mma_tf32(acc + 28, a1, b);
    }
}

// STAGE s: prefetch s+1, wait for s, compute s on A-fragment A4
#define STAGE(s, A4)                                                               \
    {                                                                              \
        if ((s) + 1 < 24) {                                                        \
            load_q(sb_addr[((s) + 1) & 1], (s) + 1, tid);                          \
            asm volatile("cp.async.commit_group;");                                \
            asm volatile("cp.async.wait_group 1;" ::: "memory");                   \
        } else {                                                                   \
            asm volatile("cp.async.wait_group 0;" ::: "memory");                   \
        }                                                                          \
        __syncthreads();                                                           \
        compute_q(acc, A4, ((s) & 1) ? sB1_4 : sB0_4, ((s) & 3) * 4,               \
                  warpM, warpN, lane);                                             \
        __syncthreads();                                                           \
    }

__global__ __launch_bounds__(256, 2)
void fused_gru_kernel(const float* __restrict__ atom_state,
                      const float* __restrict__ bias,
                      float* __restrict__ out) {
    extern __shared__ unsigned char smem[];
    uint32_t* sAH = reinterpret_cast<uint32_t*>(smem + SM_AH);
    uint32_t* sAG = reinterpret_cast<uint32_t*>(smem + SM_AG);
    const uint4* sAH4 = reinterpret_cast<const uint4*>(smem + SM_AH);
    const uint4* sAG4 = reinterpret_cast<const uint4*>(smem + SM_AG);
    const uint4* sB0_4 = reinterpret_cast<const uint4*>(smem + SM_SB0);
    const uint4* sB1_4 = reinterpret_cast<const uint4*>(smem + SM_SB1);
    float* sBias = reinterpret_cast<float*>(smem + SM_BIAS);
    uint32_t sb_addr[2];
    sb_addr[0] = (uint32_t)__cvta_generic_to_shared(smem + SM_SB0);
    sb_addr[1] = (uint32_t)__cvta_generic_to_shared(smem + SM_SB1);

    const int tid   = threadIdx.x;
    const int lane  = tid & 31;
    const int warp  = tid >> 5;
    const int warpM = warp >> 2;   // 0..1
    const int warpN = warp & 3;    // 0..3
    const int gID   = lane >> 2;
    const int tig   = lane & 3;
    const int row0  = blockIdx.x * 64;

    // prefetch stage 0 first
    load_q(sb_addr[0], 0, tid);
    asm volatile("cp.async.commit_group;");

    // A fragments: h and agg; combined biases
    build_A(sAH, atom_state, row0, tid);
    build_A(sAG, g_agg, row0, tid);
    if (tid < 128) {
        sBias[tid]       = bias[tid]       + bias[384 + tid];         // z
        sBias[128 + tid] = bias[128 + tid] + bias[384 + 128 + tid];   // r
        sBias[256 + tid] = bias[256 + tid];                           // x_h
        sBias[384 + tid] = bias[384 + 256 + tid];                     // r_h
    }

    float Z[32], R[32], acc[32];

    // ---- gate z: acc = h@U0 + agg@W0 (stages 0..7) ----
#pragma unroll
    for (int u = 0; u < 32; u++) acc[u] = 0.f;
    STAGE(0, sAH4) STAGE(1, sAH4) STAGE(2, sAH4) STAGE(3, sAH4)
    STAGE(4, sAG4) STAGE(5, sAG4) STAGE(6, sAG4) STAGE(7, sAG4)
#pragma unroll
    for (int u = 0; u < 32; u++) {
        const int j = (u >> 2) & 3, c = u & 3;
        const int col = warpN * 32 + j * 8 + tig * 2 + (c & 1);
        Z[u] = sigmoidf_fast(acc[u] + sBias[col]);
    }

    // ---- gate r: acc = h@U1 + agg@W1 (stages 8..15) ----
#pragma unroll
    for (int u = 0; u < 32; u++) acc[u] = 0.f;
    STAGE(8, sAH4)  STAGE(9, sAH4)  STAGE(10, sAH4) STAGE(11, sAH4)
    STAGE(12, sAG4) STAGE(13, sAG4) STAGE(14, sAG4) STAGE(15, sAG4)
#pragma unroll
    for (int u = 0; u < 32; u++) {
        const int j = (u >> 2) & 3, c = u & 3;
        const int col = warpN * 32 + j * 8 + tig * 2 + (c & 1);
        R[u] = sigmoidf_fast(acc[u] + sBias[128 + col]);
    }

    // ---- gate hh: acc = h@U2; acc := R*(acc+b); acc += agg@W2 (16..23) ----
#pragma unroll
    for (int u = 0; u < 32; u++) acc[u] = 0.f;
    STAGE(16, sAH4) STAGE(17, sAH4) STAGE(18, sAH4) STAGE(19, sAH4)
#pragma unroll
    for (int u = 0; u < 32; u++) {
        const int j = (u >> 2) & 3, c = u & 3;
        const int col = warpN * 32 + j * 8 + tig * 2 + (c & 1);
        acc[u] = R[u] * (acc[u] + sBias[384 + col]);
    }
    STAGE(20, sAG4) STAGE(21, sAG4) STAGE(22, sAG4) STAGE(23, sAG4)

    // ---- combine + store ----
#pragma unroll
    for (int u = 0; u < 32; u++) {
        const int i = u >> 4, j = (u >> 2) & 3, c = u & 3;
        const int rt  = warpM * 32 + i * 16 + gID + ((c >> 1) << 3);
        const int col = warpN * 32 + j * 8 + tig * 2 + (c & 1);
        const float hh = tanh_safe(acc[u] + sBias[256 + col]);
        const float h  = __ldg(&atom_state[(size_t)(row0 + rt) * DD + col]);
        out[(size_t)(row0 + rt) * DD + col] = Z[u] * h + (1.0f - Z[u]) * hh;
    }
}

// ---------------------------------------------------------------------------
// launch (single stream; fork reverted)
// ---------------------------------------------------------------------------
extern "C" void kernel_launch(void* const* d_in, const int* in_sizes, int n_in,
                              void* d_out, int out_size) {
    const float* atom_state = (const float*)d_in[0];
    const float* messages   = (const float*)d_in[1];
    const int*   conn       = (const int*)d_in[2];
    const float* Wk         = (const float*)d_in[3];
    const float* Uk         = (const float*)d_in[4];
    const float* bias       = (const float*)d_in[5];
    float*       out        = (float*)d_out;
    (void)in_sizes; (void)n_in; (void)out_size;

    cudaFuncSetAttribute(fused_gru_kernel,
                         cudaFuncAttributeMaxDynamicSharedMemorySize, SMEM_TOTAL);

    void* agg_ptr = nullptr;
    cudaGetSymbolAddress(&agg_ptr, g_agg);

    convert_B_kernel<<<96, 256>>>(Wk, Uk);
    cudaMemsetAsync(agg_ptr, 0, (size_t)MM * DD * sizeof(float));
    scatter_kernel<<<NEDGE / 8, 256>>>(messages, conn);
    fused_gru_kernel<<<MM / 64, 256, SMEM_TOTAL>>>(atom_state, bias, out);
}